// round 3
// baseline (speedup 1.0000x reference)
#include <cuda_runtime.h>
#include <cstdint>

#define N_ENC     16384
#define N_LEVELS  16
#define HMASK     16383u
#define P2C       2654435761u
#define P3C       805459861u
#define TILES     37
#define THREADS   512

// Precomputed fp32-faithful replication of
// ceil(exp(linspace(log(16f), log(512f), 16))):
__constant__ int c_res[N_LEVELS] = {16, 21, 26, 32, 41, 51, 64, 81,
                                    102, 128, 162, 204, 256, 323, 407, 512};

// Per-level tables, transposed+packed:
// g_tables[level][n] = (emb[0][n][level], emb[1][n][level])
__device__ float2 g_tables[N_LEVELS][N_ENC];   // 2 MB static scratch (allowed)

// ---------------------------------------------------------------------------
// Pass 1: pack embmatrix (E=2, N_ENC, L=16) into level-major float2 tables so
// the main kernel's SMEM stage is a contiguous 128 KB copy.
// ---------------------------------------------------------------------------
__global__ void pack_tables_kernel(const float* __restrict__ emb) {
    int i = blockIdx.x * blockDim.x + threadIdx.x;
    if (i < N_LEVELS * N_ENC) {
        int l = i & (N_LEVELS - 1);
        int n = i >> 4;
        float e0 = emb[n * N_LEVELS + l];
        float e1 = emb[N_ENC * N_LEVELS + n * N_LEVELS + l];
        g_tables[l][n] = make_float2(e0, e1);
    }
}

// ---------------------------------------------------------------------------
// Pass 2: main encode. Grid = TILES*16 blocks, bid = tile*16 + level so the 16
// level-CTAs of a tile are temporally adjacent (L2 write-sector merging on the
// 128B-per-point output rows). One CTA stages its level's 128 KB table into
// dynamic SMEM, then streams its point tile.
// ---------------------------------------------------------------------------
__global__ void __launch_bounds__(THREADS, 1)
hash_enc_kernel(const float* __restrict__ x, float2* __restrict__ out,
                int npoints, int ppt) {
    extern __shared__ float2 s_tab[];   // 16384 * 8B = 128 KB

    const int level = blockIdx.x & (N_LEVELS - 1);
    const int tile  = blockIdx.x >> 4;

    // Stage table: contiguous float4 copy, 16 iters/thread.
    {
        const float4* __restrict__ src = reinterpret_cast<const float4*>(g_tables[level]);
        float4* dst = reinterpret_cast<float4*>(s_tab);
        for (int i = threadIdx.x; i < (N_ENC * 2) / 4; i += THREADS)
            dst[i] = src[i];
    }
    __syncthreads();

    const int   res  = c_res[level];
    const float resf = (float)res;
    const int   p0   = tile * ppt;
    const int   p1   = (p0 + ppt < npoints) ? (p0 + ppt) : npoints;

    for (int p = p0 + threadIdx.x; p < p1; p += THREADS) {
        const float xi = x[3 * p + 0];
        const float yi = x[3 * p + 1];
        const float zi = x[3 * p + 2];

        // align_corners=False unnormalization, same op order as reference
        const float px = ((xi + 1.0f) * resf - 1.0f) * 0.5f;
        const float py = ((yi + 1.0f) * resf - 1.0f) * 0.5f;
        const float pz = ((zi + 1.0f) * resf - 1.0f) * 0.5f;

        const float fxf = floorf(px), fyf = floorf(py), fzf = floorf(pz);
        const float fx = px - fxf, fy = py - fyf, fz = pz - fzf;
        const int ix = (int)fxf, iy = (int)fyf, iz = (int)fzf;

        // Per-dim weights with validity folded in.
        // ix ∈ [-1, res-1]: side0 invalid iff ix<0; side1 invalid iff ix+1>=res.
        const float wx0 = (ix >= 0)       ? (1.0f - fx) : 0.0f;
        const float wx1 = (ix < res - 1)  ? fx          : 0.0f;
        const float wy0 = (iy >= 0)       ? (1.0f - fy) : 0.0f;
        const float wy1 = (iy < res - 1)  ? fy          : 0.0f;
        const float wz0 = (iz >= 0)       ? (1.0f - fz) : 0.0f;
        const float wz1 = (iz < res - 1)  ? fz          : 0.0f;

        // Hash: h = (z_corner ^ y_corner*P2 ^ x_corner*P3) & HMASK.
        const unsigned ax0 = (unsigned)ix * P3C;  const unsigned ax1 = ax0 + P3C;
        const unsigned ay0 = (unsigned)iy * P2C;  const unsigned ay1 = ay0 + P2C;
        const unsigned az0 = (unsigned)iz;        const unsigned az1 = az0 + 1u;

        const unsigned hyz00 = az0 ^ ay0;
        const unsigned hyz01 = az1 ^ ay0;
        const unsigned hyz10 = az0 ^ ay1;
        const unsigned hyz11 = az1 ^ ay1;

        const float wyz00 = wy0 * wz0;
        const float wyz01 = wy0 * wz1;
        const float wyz10 = wy1 * wz0;
        const float wyz11 = wy1 * wz1;

        // 8 gathers, issued back-to-back (independent LDS.64 chains) then FMA'd.
        const float2 v0 = s_tab[(hyz00 ^ ax0) & HMASK];
        const float2 v1 = s_tab[(hyz01 ^ ax0) & HMASK];
        const float2 v2 = s_tab[(hyz10 ^ ax0) & HMASK];
        const float2 v3 = s_tab[(hyz11 ^ ax0) & HMASK];
        const float2 v4 = s_tab[(hyz00 ^ ax1) & HMASK];
        const float2 v5 = s_tab[(hyz01 ^ ax1) & HMASK];
        const float2 v6 = s_tab[(hyz10 ^ ax1) & HMASK];
        const float2 v7 = s_tab[(hyz11 ^ ax1) & HMASK];

        const float w0 = wx0 * wyz00;
        const float w1 = wx0 * wyz01;
        const float w2 = wx0 * wyz10;
        const float w3 = wx0 * wyz11;
        const float w4 = wx1 * wyz00;
        const float w5 = wx1 * wyz01;
        const float w6 = wx1 * wyz10;
        const float w7 = wx1 * wyz11;

        float accx = w0 * v0.x, accy = w0 * v0.y;
        accx += w1 * v1.x;  accy += w1 * v1.y;
        accx += w2 * v2.x;  accy += w2 * v2.y;
        accx += w3 * v3.x;  accy += w3 * v3.y;
        accx += w4 * v4.x;  accy += w4 * v4.y;
        accx += w5 * v5.x;  accy += w5 * v5.y;
        accx += w6 * v6.x;  accy += w6 * v6.y;
        accx += w7 * v7.x;  accy += w7 * v7.y;

        out[(size_t)p * N_LEVELS + level] = make_float2(accx, accy);
    }
}

extern "C" void kernel_launch(void* const* d_in, const int* in_sizes, int n_in,
                              void* d_out, int out_size) {
    // metadata order: x (B*3 floats), embmatrix (2*16384*16 floats).
    // Defensive: identify by size in case order differs.
    const float* x   = (const float*)d_in[0];
    const float* emb = (const float*)d_in[1];
    int nx = in_sizes[0];
    if (n_in >= 2 && in_sizes[0] == 2 * N_ENC * N_LEVELS && in_sizes[1] != 2 * N_ENC * N_LEVELS) {
        emb = (const float*)d_in[0];
        x   = (const float*)d_in[1];
        nx  = in_sizes[1];
    }
    const int npoints = nx / 3;

    // Opt in to >48 KB dynamic SMEM (idempotent; legal during graph capture).
    cudaFuncSetAttribute(hash_enc_kernel,
                         cudaFuncAttributeMaxDynamicSharedMemorySize,
                         N_ENC * (int)sizeof(float2));

    pack_tables_kernel<<<(N_LEVELS * N_ENC + 255) / 256, 256>>>(emb);

    const int ppt = (npoints + TILES - 1) / TILES;
    hash_enc_kernel<<<TILES * N_LEVELS, THREADS, N_ENC * sizeof(float2)>>>(
        x, (float2*)d_out, npoints, ppt);
}

// round 5
// speedup vs baseline: 1.2217x; 1.2217x over previous
#include <cuda_runtime.h>
#include <cuda_fp16.h>
#include <cstdint>

#define N_ENC     16384
#define N_LEVELS  16
#define HMASK     16383u
#define P2C       2654435761u
#define P3C       805459861u
#define TILES     37
#define THREADS   512

// Precomputed fp32-faithful replication of
// ceil(exp(linspace(log(16f), log(512f), 16))):
__constant__ int c_res[N_LEVELS] = {16, 21, 26, 32, 41, 51, 64, 81,
                                    102, 128, 162, 204, 256, 323, 407, 512};

// Per-level tables, transposed + packed fp16x2:
// g_tables[level][n] = half2(emb[0][n][level], emb[1][n][level])
__device__ __half2 g_tables[N_LEVELS][N_ENC];   // 1 MB static scratch (allowed)

// ---------------------------------------------------------------------------
// Pass 1: pack embmatrix (E=2, N_ENC, L=16) into level-major half2 tables.
// ---------------------------------------------------------------------------
__global__ void pack_tables_kernel(const float* __restrict__ emb) {
    int i = blockIdx.x * blockDim.x + threadIdx.x;
    if (i < N_LEVELS * N_ENC) {
        int l = i & (N_LEVELS - 1);
        int n = i >> 4;
        float e0 = emb[n * N_LEVELS + l];
        float e1 = emb[N_ENC * N_LEVELS + n * N_LEVELS + l];
        g_tables[l][n] = __floats2half2_rn(e0, e1);
    }
}

// ---------------------------------------------------------------------------
// Pass 2: main encode. Each CTA owns one (tile, level); its 64 KB fp16x2 table
// lives in dynamic SMEM so every gather is a single-phase LDS.32 (4B) instead
// of the two-phase LDS.64 that cost ~9 wavefronts/gather in the fp32 version.
// 2 CTAs/SM (128 KB total SMEM), grid = 592 = 2 exact waves of 296.
// ---------------------------------------------------------------------------
__global__ void __launch_bounds__(THREADS, 2)
hash_enc_kernel(const float* __restrict__ x, float2* __restrict__ out,
                int npoints, int ppt) {
    extern __shared__ unsigned s_tab[];   // 16384 * 4B = 64 KB

    const int level = blockIdx.x & (N_LEVELS - 1);
    const int tile  = blockIdx.x >> 4;

    // Stage table: contiguous 16B copies, 8 iters/thread.
    {
        const float4* __restrict__ src = reinterpret_cast<const float4*>(g_tables[level]);
        float4* dst = reinterpret_cast<float4*>(s_tab);
        for (int i = threadIdx.x; i < N_ENC / 4; i += THREADS)
            dst[i] = src[i];
    }
    __syncthreads();

    const int   res  = c_res[level];
    const float resf = (float)res;
    const int   p0   = tile * ppt;
    const int   p1   = (p0 + ppt < npoints) ? (p0 + ppt) : npoints;

    for (int p = p0 + threadIdx.x; p < p1; p += THREADS) {
        const float xi = x[3 * p + 0];
        const float yi = x[3 * p + 1];
        const float zi = x[3 * p + 2];

        // align_corners=False unnormalization, same op order as reference
        const float px = ((xi + 1.0f) * resf - 1.0f) * 0.5f;
        const float py = ((yi + 1.0f) * resf - 1.0f) * 0.5f;
        const float pz = ((zi + 1.0f) * resf - 1.0f) * 0.5f;

        const float fxf = floorf(px), fyf = floorf(py), fzf = floorf(pz);
        const float fx = px - fxf, fy = py - fyf, fz = pz - fzf;
        const int ix = (int)fxf, iy = (int)fyf, iz = (int)fzf;

        // Per-dim weights with zero-padding validity folded in.
        const float wx0 = (ix >= 0)       ? (1.0f - fx) : 0.0f;
        const float wx1 = (ix < res - 1)  ? fx          : 0.0f;
        const float wy0 = (iy >= 0)       ? (1.0f - fy) : 0.0f;
        const float wy1 = (iy < res - 1)  ? fy          : 0.0f;
        const float wz0 = (iz >= 0)       ? (1.0f - fz) : 0.0f;
        const float wz1 = (iz < res - 1)  ? fz          : 0.0f;

        // Hash: h = (z ^ y*P2 ^ x*P3) & HMASK.
        const unsigned ax0 = (unsigned)ix * P3C;  const unsigned ax1 = ax0 + P3C;
        const unsigned ay0 = (unsigned)iy * P2C;  const unsigned ay1 = ay0 + P2C;
        const unsigned az0 = (unsigned)iz;        const unsigned az1 = az0 + 1u;

        const unsigned hyz00 = az0 ^ ay0;
        const unsigned hyz01 = az1 ^ ay0;
        const unsigned hyz10 = az0 ^ ay1;
        const unsigned hyz11 = az1 ^ ay1;

        const float wyz00 = wy0 * wz0;
        const float wyz01 = wy0 * wz1;
        const float wyz10 = wy1 * wz0;
        const float wyz11 = wy1 * wz1;

        // 8 independent single-phase LDS.32 gathers.
        const unsigned u0 = s_tab[(hyz00 ^ ax0) & HMASK];
        const unsigned u1 = s_tab[(hyz01 ^ ax0) & HMASK];
        const unsigned u2 = s_tab[(hyz10 ^ ax0) & HMASK];
        const unsigned u3 = s_tab[(hyz11 ^ ax0) & HMASK];
        const unsigned u4 = s_tab[(hyz00 ^ ax1) & HMASK];
        const unsigned u5 = s_tab[(hyz01 ^ ax1) & HMASK];
        const unsigned u6 = s_tab[(hyz10 ^ ax1) & HMASK];
        const unsigned u7 = s_tab[(hyz11 ^ ax1) & HMASK];

        const float w0 = wx0 * wyz00;
        const float w1 = wx0 * wyz01;
        const float w2 = wx0 * wyz10;
        const float w3 = wx0 * wyz11;
        const float w4 = wx1 * wyz00;
        const float w5 = wx1 * wyz01;
        const float w6 = wx1 * wyz10;
        const float w7 = wx1 * wyz11;

        // fp32 accumulate (convert each half2 after gather).
        float2 v;
        v = __half22float2(*(const __half2*)&u0);
        float accx = w0 * v.x, accy = w0 * v.y;
        v = __half22float2(*(const __half2*)&u1); accx += w1 * v.x; accy += w1 * v.y;
        v = __half22float2(*(const __half2*)&u2); accx += w2 * v.x; accy += w2 * v.y;
        v = __half22float2(*(const __half2*)&u3); accx += w3 * v.x; accy += w3 * v.y;
        v = __half22float2(*(const __half2*)&u4); accx += w4 * v.x; accy += w4 * v.y;
        v = __half22float2(*(const __half2*)&u5); accx += w5 * v.x; accy += w5 * v.y;
        v = __half22float2(*(const __half2*)&u6); accx += w6 * v.x; accy += w6 * v.y;
        v = __half22float2(*(const __half2*)&u7); accx += w7 * v.x; accy += w7 * v.y;

        out[(size_t)p * N_LEVELS + level] = make_float2(accx, accy);
    }
}

extern "C" void kernel_launch(void* const* d_in, const int* in_sizes, int n_in,
                              void* d_out, int out_size) {
    const float* x   = (const float*)d_in[0];
    const float* emb = (const float*)d_in[1];
    int nx = in_sizes[0];
    if (n_in >= 2 && in_sizes[0] == 2 * N_ENC * N_LEVELS && in_sizes[1] != 2 * N_ENC * N_LEVELS) {
        emb = (const float*)d_in[0];
        x   = (const float*)d_in[1];
        nx  = in_sizes[1];
    }
    const int npoints = nx / 3;

    cudaFuncSetAttribute(hash_enc_kernel,
                         cudaFuncAttributeMaxDynamicSharedMemorySize,
                         N_ENC * (int)sizeof(unsigned));

    pack_tables_kernel<<<(N_LEVELS * N_ENC + 255) / 256, 256>>>(emb);

    const int ppt = (npoints + TILES - 1) / TILES;
    hash_enc_kernel<<<TILES * N_LEVELS, THREADS, N_ENC * sizeof(unsigned)>>>(
        x, (float2*)d_out, npoints, ppt);
}

// round 7
// speedup vs baseline: 1.8795x; 1.5385x over previous
#include <cuda_runtime.h>
#include <cuda_fp16.h>
#include <cstdint>

#define N_ENC     16384
#define N_LEVELS  16
#define HMASK     16383u
#define P2C       2654435761u
#define P3C       805459861u
#define TILES     18
#define NPAIRS    8
#define THREADS   1024

// Precomputed fp32-faithful replication of
// ceil(exp(linspace(log(16f), log(512f), 16))):
__constant__ int c_res[N_LEVELS] = {16, 21, 26, 32, 41, 51, 64, 81,
                                    102, 128, 162, 204, 256, 323, 407, 512};

// Per-level tables, transposed + packed fp16x2:
// g_tables[level][n] = half2(emb[0][n][level], emb[1][n][level])
__device__ __half2 g_tables[N_LEVELS][N_ENC];   // 1 MB static scratch (allowed)

// ---------------------------------------------------------------------------
// Pass 1: pack embmatrix (E=2, N_ENC, L=16) into level-major half2 tables.
// ---------------------------------------------------------------------------
__global__ void pack_tables_kernel(const float* __restrict__ emb) {
    int i = blockIdx.x * blockDim.x + threadIdx.x;
    if (i < N_LEVELS * N_ENC) {
        int l = i & (N_LEVELS - 1);
        int n = i >> 4;
        float e0 = emb[n * N_LEVELS + l];
        float e1 = emb[N_ENC * N_LEVELS + n * N_LEVELS + l];
        g_tables[l][n] = __floats2half2_rn(e0, e1);
    }
}

// One level's trilinear hashed interpolation out of an SMEM fp16x2 table.
__device__ __forceinline__ float2 interp_level(const unsigned* __restrict__ tab,
                                               int res, float xi, float yi, float zi) {
    const float resf = (float)res;
    const float px = ((xi + 1.0f) * resf - 1.0f) * 0.5f;
    const float py = ((yi + 1.0f) * resf - 1.0f) * 0.5f;
    const float pz = ((zi + 1.0f) * resf - 1.0f) * 0.5f;

    const float fxf = floorf(px), fyf = floorf(py), fzf = floorf(pz);
    const float fx = px - fxf, fy = py - fyf, fz = pz - fzf;
    const int ix = (int)fxf, iy = (int)fyf, iz = (int)fzf;

    // Per-dim weights with zero-padding validity folded in.
    const float wx0 = (ix >= 0)       ? (1.0f - fx) : 0.0f;
    const float wx1 = (ix < res - 1)  ? fx          : 0.0f;
    const float wy0 = (iy >= 0)       ? (1.0f - fy) : 0.0f;
    const float wy1 = (iy < res - 1)  ? fy          : 0.0f;
    const float wz0 = (iz >= 0)       ? (1.0f - fz) : 0.0f;
    const float wz1 = (iz < res - 1)  ? fz          : 0.0f;

    // Hash: h = (z ^ y*P2 ^ x*P3) & HMASK.
    const unsigned ax0 = (unsigned)ix * P3C;  const unsigned ax1 = ax0 + P3C;
    const unsigned ay0 = (unsigned)iy * P2C;  const unsigned ay1 = ay0 + P2C;
    const unsigned az0 = (unsigned)iz;        const unsigned az1 = az0 + 1u;

    const unsigned hyz00 = az0 ^ ay0;
    const unsigned hyz01 = az1 ^ ay0;
    const unsigned hyz10 = az0 ^ ay1;
    const unsigned hyz11 = az1 ^ ay1;

    // 8 independent single-phase LDS.32 gathers.
    const unsigned u0 = tab[(hyz00 ^ ax0) & HMASK];
    const unsigned u1 = tab[(hyz01 ^ ax0) & HMASK];
    const unsigned u2 = tab[(hyz10 ^ ax0) & HMASK];
    const unsigned u3 = tab[(hyz11 ^ ax0) & HMASK];
    const unsigned u4 = tab[(hyz00 ^ ax1) & HMASK];
    const unsigned u5 = tab[(hyz01 ^ ax1) & HMASK];
    const unsigned u6 = tab[(hyz10 ^ ax1) & HMASK];
    const unsigned u7 = tab[(hyz11 ^ ax1) & HMASK];

    const float wyz00 = wy0 * wz0;
    const float wyz01 = wy0 * wz1;
    const float wyz10 = wy1 * wz0;
    const float wyz11 = wy1 * wz1;

    const float w0 = wx0 * wyz00;
    const float w1 = wx0 * wyz01;
    const float w2 = wx0 * wyz10;
    const float w3 = wx0 * wyz11;
    const float w4 = wx1 * wyz00;
    const float w5 = wx1 * wyz01;
    const float w6 = wx1 * wyz10;
    const float w7 = wx1 * wyz11;

    float2 v;
    v = __half22float2(*(const __half2*)&u0);
    float accx = w0 * v.x, accy = w0 * v.y;
    v = __half22float2(*(const __half2*)&u1); accx += w1 * v.x; accy += w1 * v.y;
    v = __half22float2(*(const __half2*)&u2); accx += w2 * v.x; accy += w2 * v.y;
    v = __half22float2(*(const __half2*)&u3); accx += w3 * v.x; accy += w3 * v.y;
    v = __half22float2(*(const __half2*)&u4); accx += w4 * v.x; accy += w4 * v.y;
    v = __half22float2(*(const __half2*)&u5); accx += w5 * v.x; accy += w5 * v.y;
    v = __half22float2(*(const __half2*)&u6); accx += w6 * v.x; accy += w6 * v.y;
    v = __half22float2(*(const __half2*)&u7); accx += w7 * v.x; accy += w7 * v.y;

    return make_float2(accx, accy);
}

// ---------------------------------------------------------------------------
// Pass 2: each CTA owns (tile, level-pair). Two 64 KB fp16x2 tables in SMEM
// (128 KB), 1024 threads, 1 CTA/SM (32 warps, same as before). Each thread
// computes both levels for its point and writes ONE 16 B float4 — halving
// STG line-wavefronts and amortizing x-loads over 2 levels.
// Grid = 18 tiles x 8 pairs = 144 CTAs = one exact wave; tables staged once.
// ---------------------------------------------------------------------------
__global__ void __launch_bounds__(THREADS, 1)
hash_enc_kernel(const float* __restrict__ x, float4* __restrict__ out,
                int npoints, int ppt) {
    extern __shared__ unsigned s_tab[];   // 2 * 16384 * 4B = 128 KB

    const int pair = blockIdx.x & (NPAIRS - 1);
    const int tile = blockIdx.x / NPAIRS;
    const int lvl0 = pair * 2;

    // Stage both tables: g_tables[lvl0] and g_tables[lvl0+1] are contiguous.
    {
        const float4* __restrict__ src = reinterpret_cast<const float4*>(g_tables[lvl0]);
        float4* dst = reinterpret_cast<float4*>(s_tab);
        for (int i = threadIdx.x; i < (2 * N_ENC) / 4; i += THREADS)
            dst[i] = src[i];
    }
    __syncthreads();

    const unsigned* tab0 = s_tab;
    const unsigned* tab1 = s_tab + N_ENC;
    const int res0 = c_res[lvl0];
    const int res1 = c_res[lvl0 + 1];

    const int p0 = tile * ppt;
    const int p1 = (p0 + ppt < npoints) ? (p0 + ppt) : npoints;

    for (int p = p0 + threadIdx.x; p < p1; p += THREADS) {
        const float xi = x[3 * p + 0];
        const float yi = x[3 * p + 1];
        const float zi = x[3 * p + 2];

        const float2 f0 = interp_level(tab0, res0, xi, yi, zi);
        const float2 f1 = interp_level(tab1, res1, xi, yi, zi);

        // out element index (in float2 units): p*16 + lvl0 -> float4 index p*8 + pair
        out[(size_t)p * NPAIRS + pair] = make_float4(f0.x, f0.y, f1.x, f1.y);
    }
}

extern "C" void kernel_launch(void* const* d_in, const int* in_sizes, int n_in,
                              void* d_out, int out_size) {
    const float* x   = (const float*)d_in[0];
    const float* emb = (const float*)d_in[1];
    int nx = in_sizes[0];
    if (n_in >= 2 && in_sizes[0] == 2 * N_ENC * N_LEVELS && in_sizes[1] != 2 * N_ENC * N_LEVELS) {
        emb = (const float*)d_in[0];
        x   = (const float*)d_in[1];
        nx  = in_sizes[1];
    }
    const int npoints = nx / 3;

    cudaFuncSetAttribute(hash_enc_kernel,
                         cudaFuncAttributeMaxDynamicSharedMemorySize,
                         2 * N_ENC * (int)sizeof(unsigned));

    pack_tables_kernel<<<(N_LEVELS * N_ENC + 255) / 256, 256>>>(emb);

    const int ppt = (npoints + TILES - 1) / TILES;
    hash_enc_kernel<<<TILES * NPAIRS, THREADS, 2 * N_ENC * sizeof(unsigned)>>>(
        x, (float4*)d_out, npoints, ppt);
}